// round 11
// baseline (speedup 1.0000x reference)
#include <cuda_runtime.h>
#include <math.h>
#include <stdint.h>

// ---------------------------------------------------------------------------
// Problem constants
// ---------------------------------------------------------------------------
#define BB   4      // batch
#define CC   64     // C
#define EE   128    // E = 2C
#define HH   128
#define WWID 128
#define WS_  8
#define STR_ 4
#define NH_  31     // windows per dim
#define NWIN (NH_*NH_)          // 961
#define NWB  (NWIN*BB)          // 3844
#define NTOK (NWB*64)           // 246016 token rows
#define HW   (HH*WWID)          // 16384

// ---------------------------------------------------------------------------
// Scratch (static device globals; no runtime allocation)
// ---------------------------------------------------------------------------
__device__ __align__(16) float g_mid [BB*64*HW];          // conv1 out
__device__ __align__(16) float g_nhwc[BB*HW*EE];           // combined0, NHWC
__device__ __align__(16) float g_qkv [(size_t)NTOK*384];
__device__ __align__(16) float g_o2  [(size_t)NTOK*128];
__device__ __align__(16) float g_att [(size_t)NTOK*128];

// ---------------------------------------------------------------------------
// tf32 helpers
// ---------------------------------------------------------------------------
__device__ __forceinline__ uint32_t f2tf(float f) {
    uint32_t u;
    asm("cvt.rna.tf32.f32 %0, %1;" : "=r"(u) : "f"(f));
    return u;
}

__device__ __forceinline__ void mma_tf32(float* d, const uint32_t* a, const uint32_t* b) {
    asm volatile(
        "mma.sync.aligned.m16n8k8.row.col.f32.tf32.tf32.f32 "
        "{%0,%1,%2,%3}, {%4,%5,%6,%7}, {%8,%9}, {%0,%1,%2,%3};\n"
        : "+f"(d[0]), "+f"(d[1]), "+f"(d[2]), "+f"(d[3])
        : "r"(a[0]), "r"(a[1]), "r"(a[2]), "r"(a[3]), "r"(b[0]), "r"(b[1]));
}

// ---------------------------------------------------------------------------
// conv1: 3x3, 64 -> 32 per branch, ReLU.
// ---------------------------------------------------------------------------
__global__ void conv1_kernel(const float* __restrict__ vf,
                             const float* __restrict__ mw1, const float* __restrict__ mb1,
                             const float* __restrict__ aw1, const float* __restrict__ ab1)
{
    int z   = blockIdx.z;            // b*8 + br*4 + ocg
    int b   = z >> 3;
    int br  = (z >> 2) & 1;
    int ocg = z & 3;
    const float* w    = br ? aw1 : mw1;   // [32][64][9]
    const float* bias = br ? ab1 : mb1;
    int ocBase = ocg * 8;
    int x0 = blockIdx.x * 32, y0 = blockIdx.y * 16;
    int tx = threadIdx.x, ty = threadIdx.y;
    int tid = ty * 16 + tx;

    __shared__ float sh[8][18][35];
    __shared__ float wsh[8][8][9];

    float acc[8][2];
#pragma unroll
    for (int o = 0; o < 8; o++) {
        float bv = bias[ocBase + o];
        acc[o][0] = bv; acc[o][1] = bv;
    }

    const float* inBase = vf + (size_t)(b * 128 + br * 64) * HW;

    for (int ic0 = 0; ic0 < 64; ic0 += 8) {
        __syncthreads();
        for (int idx = tid; idx < 8 * 18 * 34; idx += 256) {
            int ic = idx / (18 * 34);
            int r  = idx % (18 * 34);
            int iy = r / 34, ix = r % 34;
            int gy = y0 + iy - 1, gx = x0 + ix - 1;
            float v = 0.f;
            if (gy >= 0 && gy < HH && gx >= 0 && gx < WWID)
                v = inBase[(size_t)(ic0 + ic) * HW + gy * WWID + gx];
            sh[ic][iy][ix] = v;
        }
        for (int idx = tid; idx < 8 * 8 * 9; idx += 256) {
            int o = idx / 72;
            int r = idx % 72;
            int ic = r / 9, k = r % 9;
            wsh[o][ic][k] = w[(ocBase + o) * 576 + (ic0 + ic) * 9 + k];
        }
        __syncthreads();
#pragma unroll
        for (int ic = 0; ic < 8; ic++) {
#pragma unroll
            for (int ky = 0; ky < 3; ky++) {
                float xv[4];
#pragma unroll
                for (int q = 0; q < 4; q++) xv[q] = sh[ic][ty + ky][tx * 2 + q];
#pragma unroll
                for (int kx = 0; kx < 3; kx++) {
#pragma unroll
                    for (int o = 0; o < 8; o++) {
                        float wv = wsh[o][ic][ky * 3 + kx];
                        acc[o][0] += xv[kx]     * wv;
                        acc[o][1] += xv[kx + 1] * wv;
                    }
                }
            }
        }
    }
    int y = y0 + ty, x = x0 + tx * 2;
#pragma unroll
    for (int o = 0; o < 8; o++) {
        float* p = g_mid + (size_t)(b * 64 + br * 32 + ocBase + o) * HW + y * WWID + x;
        p[0] = fmaxf(acc[o][0], 0.f);
        p[1] = fmaxf(acc[o][1], 0.f);
    }
}

// ---------------------------------------------------------------------------
// conv2: 3x3, 32 -> 64 per branch, no ReLU, writes NHWC combined0.
// ---------------------------------------------------------------------------
__global__ void conv2_kernel(const float* __restrict__ mw2, const float* __restrict__ mb2,
                             const float* __restrict__ aw2, const float* __restrict__ ab2)
{
    int z   = blockIdx.z;            // b*16 + br*8 + ocg
    int b   = z >> 4;
    int br  = (z >> 3) & 1;
    int ocg = z & 7;
    const float* w    = br ? aw2 : mw2;   // [64][32][9]
    const float* bias = br ? ab2 : mb2;
    int ocBase = ocg * 8;
    int x0 = blockIdx.x * 32, y0 = blockIdx.y * 16;
    int tx = threadIdx.x, ty = threadIdx.y;
    int tid = ty * 16 + tx;

    __shared__ float sh[8][18][35];
    __shared__ float wsh[8][8][9];

    float acc[8][2];
#pragma unroll
    for (int o = 0; o < 8; o++) {
        float bv = bias[ocBase + o];
        acc[o][0] = bv; acc[o][1] = bv;
    }

    const float* inBase = g_mid + (size_t)(b * 64 + br * 32) * HW;

    for (int ic0 = 0; ic0 < 32; ic0 += 8) {
        __syncthreads();
        for (int idx = tid; idx < 8 * 18 * 34; idx += 256) {
            int ic = idx / (18 * 34);
            int r  = idx % (18 * 34);
            int iy = r / 34, ix = r % 34;
            int gy = y0 + iy - 1, gx = x0 + ix - 1;
            float v = 0.f;
            if (gy >= 0 && gy < HH && gx >= 0 && gx < WWID)
                v = inBase[(size_t)(ic0 + ic) * HW + gy * WWID + gx];
            sh[ic][iy][ix] = v;
        }
        for (int idx = tid; idx < 8 * 8 * 9; idx += 256) {
            int o = idx / 72;
            int r = idx % 72;
            int ic = r / 9, k = r % 9;
            wsh[o][ic][k] = w[(ocBase + o) * 288 + (ic0 + ic) * 9 + k];
        }
        __syncthreads();
#pragma unroll
        for (int ic = 0; ic < 8; ic++) {
#pragma unroll
            for (int ky = 0; ky < 3; ky++) {
                float xv[4];
#pragma unroll
                for (int q = 0; q < 4; q++) xv[q] = sh[ic][ty + ky][tx * 2 + q];
#pragma unroll
                for (int kx = 0; kx < 3; kx++) {
#pragma unroll
                    for (int o = 0; o < 8; o++) {
                        float wv = wsh[o][ic][ky * 3 + kx];
                        acc[o][0] += xv[kx]     * wv;
                        acc[o][1] += xv[kx + 1] * wv;
                    }
                }
            }
        }
    }
    int y = y0 + ty, x = x0 + tx * 2;
    int e0 = br * 64 + ocBase;
#pragma unroll
    for (int px = 0; px < 2; px++) {
        float4 f0 = make_float4(acc[0][px], acc[1][px], acc[2][px], acc[3][px]);
        float4 f1 = make_float4(acc[4][px], acc[5][px], acc[6][px], acc[7][px]);
        float* p = g_nhwc + ((size_t)(b * HH + y) * WWID + (x + px)) * EE + e0;
        reinterpret_cast<float4*>(p)[0] = f0;
        reinterpret_cast<float4*>(p)[1] = f1;
    }
}

// ---------------------------------------------------------------------------
// tf32 tensor-core GEMM: C[M x N] = A[M x 128] * Wt[N x 128]^T + bias.
// ---------------------------------------------------------------------------
template<bool GATHER>
__global__ __launch_bounds__(256)
void gemm_tf32_kernel(const float* __restrict__ A, const float* __restrict__ Wt,
                      const float* __restrict__ bias, float* __restrict__ C, int N)
{
    __shared__ uint32_t As[32][136];
    __shared__ uint32_t Bs[32][136];

    int tid  = threadIdx.x;
    int lane = tid & 31;
    int wid  = tid >> 5;
    int wm = wid & 1;
    int wn = wid >> 1;
    int m0 = blockIdx.y * 128;
    int n0 = blockIdx.x * 128;

    float acc[4][4][4];
#pragma unroll
    for (int mt = 0; mt < 4; mt++)
#pragma unroll
        for (int nt = 0; nt < 4; nt++)
#pragma unroll
            for (int r = 0; r < 4; r++) acc[mt][nt][r] = 0.f;

    int q = tid & 7;
    const float* arow[4];
    const float* brow[4];
    int rowIdx[4];
#pragma unroll
    for (int s = 0; s < 4; s++) {
        int row = (tid >> 3) + 32 * s;
        rowIdx[s] = row;
        if (GATHER) {
            int m  = m0 + row;
            int l  = m & 63;
            int wb = m >> 6;
            int b  = wb & 3;
            int win = wb >> 2;
            int hi = win / 31;
            int wi = win - hi * 31;
            int h  = hi * 4 + (l >> 3);
            int wc = wi * 4 + (l & 7);
            arow[s] = g_nhwc + ((size_t)((b * 128 + h) * 128 + wc)) * 128;
        } else {
            arow[s] = A + (size_t)(m0 + row) * 128;
        }
        brow[s] = Wt + (size_t)(n0 + row) * 128;
    }

    for (int k0 = 0; k0 < 128; k0 += 32) {
        __syncthreads();
#pragma unroll
        for (int s = 0; s < 4; s++) {
#pragma unroll
            for (int c = 0; c < 4; c++) {
                int k = q + 8 * c;
                As[k][rowIdx[s]] = f2tf(arow[s][k0 + k]);
                Bs[k][rowIdx[s]] = f2tf(brow[s][k0 + k]);
            }
        }
        __syncthreads();

#pragma unroll
        for (int kk = 0; kk < 4; kk++) {
            int c = lane & 3;
            int g = lane >> 2;
            uint32_t a[4][4], b[4][2];
#pragma unroll
            for (int mt = 0; mt < 4; mt++) {
                int r = wm * 64 + mt * 16 + g;
                a[mt][0] = As[kk * 8 + c    ][r];
                a[mt][1] = As[kk * 8 + c    ][r + 8];
                a[mt][2] = As[kk * 8 + c + 4][r];
                a[mt][3] = As[kk * 8 + c + 4][r + 8];
            }
#pragma unroll
            for (int nt = 0; nt < 4; nt++) {
                int n = wn * 32 + nt * 8 + g;
                b[nt][0] = Bs[kk * 8 + c    ][n];
                b[nt][1] = Bs[kk * 8 + c + 4][n];
            }
#pragma unroll
            for (int mt = 0; mt < 4; mt++)
#pragma unroll
                for (int nt = 0; nt < 4; nt++)
                    mma_tf32(acc[mt][nt], a[mt], b[nt]);
        }
    }

    int g  = lane >> 2;
    int c2 = (lane & 3) * 2;
#pragma unroll
    for (int mt = 0; mt < 4; mt++) {
        int row = m0 + wm * 64 + mt * 16 + g;
#pragma unroll
        for (int nt = 0; nt < 4; nt++) {
            int col = n0 + wn * 32 + nt * 8 + c2;
            float b0 = __ldg(bias + col);
            float b1 = __ldg(bias + col + 1);
            float2 v0 = make_float2(acc[mt][nt][0] + b0, acc[mt][nt][1] + b1);
            float2 v1 = make_float2(acc[mt][nt][2] + b0, acc[mt][nt][3] + b1);
            *reinterpret_cast<float2*>(C + (size_t)row * N + col)       = v0;
            *reinterpret_cast<float2*>(C + (size_t)(row + 8) * N + col) = v1;
        }
    }
}

// ---------------------------------------------------------------------------
// Attention core (tensor cores, register softmax): one block (128 thr) per
// (window*batch, head).  S = Q K^T (mma tf32), softmax entirely in registers
// (shfl reductions over the 4 lanes sharing g), P re-laid to A-fragments via
// shuffles, O = P V (mma tf32).  No smem staging of S at all.
// ---------------------------------------------------------------------------
__global__ __launch_bounds__(128)
void attn_kernel()
{
    __shared__ uint32_t qsT[32][72];   // [d][l]
    __shared__ uint32_t ksT[32][72];   // [d][m]
    __shared__ uint32_t vs [64][40];   // [m][d]

    int bx   = blockIdx.x;
    int head = bx & 3;
    int wb   = bx >> 2;
    int rowBase = wb * 64;
    int tid  = threadIdx.x;
    int lane = tid & 31;
    int warp = tid >> 5;
    const float scale = 0.17677669529663687f;  // 1/sqrt(32)
    const unsigned FULL = 0xffffffffu;

    // ---- load Q,K,V (each thread: one l-row, 16 d's) ----
    {
        int l     = tid & 63;
        int dbase = (tid >> 6) * 16;
        const float* p = g_qkv + (size_t)(rowBase + l) * 384 + head * 32 + dbase;
#pragma unroll
        for (int j4 = 0; j4 < 4; j4++) {
            float4 qv = *reinterpret_cast<const float4*>(p + j4 * 4);
            float4 kv = *reinterpret_cast<const float4*>(p + 128 + j4 * 4);
            float4 vv = *reinterpret_cast<const float4*>(p + 256 + j4 * 4);
            int d = dbase + j4 * 4;
            qsT[d + 0][l] = f2tf(qv.x * scale);
            qsT[d + 1][l] = f2tf(qv.y * scale);
            qsT[d + 2][l] = f2tf(qv.z * scale);
            qsT[d + 3][l] = f2tf(qv.w * scale);
            ksT[d + 0][l] = f2tf(kv.x);
            ksT[d + 1][l] = f2tf(kv.y);
            ksT[d + 2][l] = f2tf(kv.z);
            ksT[d + 3][l] = f2tf(kv.w);
            uint4 vt;
            vt.x = f2tf(vv.x); vt.y = f2tf(vv.y);
            vt.z = f2tf(vv.z); vt.w = f2tf(vv.w);
            *reinterpret_cast<uint4*>(&vs[l][d]) = vt;
        }
    }
    __syncthreads();

    int g = lane >> 2, c = lane & 3;
    int lbase = warp * 16;

    // ---- S = Q K^T : warp handles rows lbase..lbase+15 (l), all 64 m ----
    // sacc[nt]: d0=(l=lbase+g, m=nt*8+2c), d1=(.., 2c+1), d2=(l+8, 2c), d3=(l+8, 2c+1)
    float sacc[8][4];
#pragma unroll
    for (int nt = 0; nt < 8; nt++)
#pragma unroll
        for (int r = 0; r < 4; r++) sacc[nt][r] = 0.f;

#pragma unroll
    for (int kk = 0; kk < 4; kk++) {
        uint32_t a[4];
        a[0] = qsT[kk * 8 + c    ][lbase + g];
        a[1] = qsT[kk * 8 + c    ][lbase + g + 8];
        a[2] = qsT[kk * 8 + c + 4][lbase + g];
        a[3] = qsT[kk * 8 + c + 4][lbase + g + 8];
#pragma unroll
        for (int nt = 0; nt < 8; nt++) {
            uint32_t b[2];
            b[0] = ksT[kk * 8 + c    ][nt * 8 + g];
            b[1] = ksT[kk * 8 + c + 4][nt * 8 + g];
            mma_tf32(sacc[nt], a, b);
        }
    }

    // ---- softmax in registers over m, per row ----
    // Row A = lbase+g (regs 0,1), Row B = lbase+g+8 (regs 2,3).
    // The 64 m-values of a row live in the 4 lanes sharing g (lane bits 0-1).
    {
        float mxA = -1e30f, mxB = -1e30f;
#pragma unroll
        for (int nt = 0; nt < 8; nt++) {
            mxA = fmaxf(mxA, fmaxf(sacc[nt][0], sacc[nt][1]));
            mxB = fmaxf(mxB, fmaxf(sacc[nt][2], sacc[nt][3]));
        }
        mxA = fmaxf(mxA, __shfl_xor_sync(FULL, mxA, 1));
        mxA = fmaxf(mxA, __shfl_xor_sync(FULL, mxA, 2));
        mxB = fmaxf(mxB, __shfl_xor_sync(FULL, mxB, 1));
        mxB = fmaxf(mxB, __shfl_xor_sync(FULL, mxB, 2));

        float sA = 0.f, sB = 0.f;
#pragma unroll
        for (int nt = 0; nt < 8; nt++) {
            float e0 = __expf(sacc[nt][0] - mxA);
            float e1 = __expf(sacc[nt][1] - mxA);
            float e2 = __expf(sacc[nt][2] - mxB);
            float e3 = __expf(sacc[nt][3] - mxB);
            sacc[nt][0] = e0; sacc[nt][1] = e1;
            sacc[nt][2] = e2; sacc[nt][3] = e3;
            sA += e0 + e1;
            sB += e2 + e3;
        }
        sA += __shfl_xor_sync(FULL, sA, 1);
        sA += __shfl_xor_sync(FULL, sA, 2);
        sB += __shfl_xor_sync(FULL, sB, 1);
        sB += __shfl_xor_sync(FULL, sB, 2);
        float invA = 1.f / sA, invB = 1.f / sB;
        // convert P to tf32 bits in place
#pragma unroll
        for (int nt = 0; nt < 8; nt++) {
            sacc[nt][0] = __uint_as_float(f2tf(sacc[nt][0] * invA));
            sacc[nt][1] = __uint_as_float(f2tf(sacc[nt][1] * invA));
            sacc[nt][2] = __uint_as_float(f2tf(sacc[nt][2] * invB));
            sacc[nt][3] = __uint_as_float(f2tf(sacc[nt][3] * invB));
        }
    }

    // ---- O = P V : K=m (8 chunks), M=l, N=32 d; P A-frags built via shfl ----
    {
        float oacc[4][4];
#pragma unroll
        for (int nt = 0; nt < 4; nt++)
#pragma unroll
            for (int r = 0; r < 4; r++) oacc[nt][r] = 0.f;

        int src1 = (lane & ~3) | (c >> 1);   // lane holding m = c (as 2c'/2c'+1)
        int src2 = src1 + 2;                  // lane holding m = c+4
        bool odd = (c & 1);

#pragma unroll
        for (int kk = 0; kk < 8; kk++) {
            // A-frag target: a0=(l=g, k=c), a1=(l=g+8, k=c), a2=(l=g, k=c+4), a3=(l=g+8, k=c+4)
            uint32_t p0 = __float_as_uint(sacc[kk][0]);
            uint32_t p1 = __float_as_uint(sacc[kk][1]);
            uint32_t p2 = __float_as_uint(sacc[kk][2]);
            uint32_t p3 = __float_as_uint(sacc[kk][3]);
            uint32_t w00 = __shfl_sync(FULL, p0, src1);
            uint32_t w01 = __shfl_sync(FULL, p1, src1);
            uint32_t w10 = __shfl_sync(FULL, p2, src1);
            uint32_t w11 = __shfl_sync(FULL, p3, src1);
            uint32_t w20 = __shfl_sync(FULL, p0, src2);
            uint32_t w21 = __shfl_sync(FULL, p1, src2);
            uint32_t w30 = __shfl_sync(FULL, p2, src2);
            uint32_t w31 = __shfl_sync(FULL, p3, src2);
            uint32_t a[4];
            a[0] = odd ? w01 : w00;
            a[1] = odd ? w11 : w10;
            a[2] = odd ? w21 : w20;
            a[3] = odd ? w31 : w30;
#pragma unroll
            for (int nt = 0; nt < 4; nt++) {
                uint32_t b[2];
                b[0] = vs[kk * 8 + c    ][nt * 8 + g];
                b[1] = vs[kk * 8 + c + 4][nt * 8 + g];
                mma_tf32(oacc[nt], a, b);
            }
        }

        // write g_o2[(rowBase+l)*128 + head*32 + d]
        int c2 = c * 2;
#pragma unroll
        for (int nt = 0; nt < 4; nt++) {
            int d = head * 32 + nt * 8 + c2;
            float2 v0 = make_float2(oacc[nt][0], oacc[nt][1]);
            float2 v1 = make_float2(oacc[nt][2], oacc[nt][3]);
            *reinterpret_cast<float2*>(g_o2 + (size_t)(rowBase + lbase + g) * 128 + d)     = v0;
            *reinterpret_cast<float2*>(g_o2 + (size_t)(rowBase + lbase + g + 8) * 128 + d) = v1;
        }
    }
}

// ---------------------------------------------------------------------------
// Blend (analytic scan) + 1x1 conv (smem-staged) + sigmoid gate + residual.
// ---------------------------------------------------------------------------
__global__ void blend_kernel(const float* __restrict__ fcw, const float* __restrict__ fcb,
                             const float* __restrict__ vf, float* __restrict__ out)
{
    __shared__ float enh[32][129];
    __shared__ float fw [32][65];
    __shared__ float fcs[128][76];
    __shared__ float fbs[64];

    int wc = blockIdx.x;     // 0..3
    int h  = blockIdx.y;     // 0..127
    int b  = blockIdx.z;     // 0..3
    int w0 = wc * 32;
    int tid = threadIdx.x;

    for (int idx = tid; idx < 64 * 128; idx += 256) {
        int c = idx >> 7, e = idx & 127;
        fcs[e][c] = fcw[idx];
    }
    if (tid < 64) fbs[tid] = fcb[tid];

    int hiLo = max(0, (h - 4) >> 2);
    int hiHi = min(NH_ - 1, h >> 2);

    for (int s = 0; s < 16; s++) {
        int idx = tid + s * 256;
        int px = idx >> 7;
        int e  = idx & 127;
        int wpix = w0 + px;
        int wiLo = max(0, (wpix - 4) >> 2);
        int wiHi = min(NH_ - 1, wpix >> 2);

        float val = g_nhwc[((size_t)(b * HH + h) * WWID + wpix) * EE + e];
        for (int hi = hiLo; hi <= hiHi; hi++) {
            int lr = (h - hi * 4) * 8;
            for (int wi = wiLo; wi <= wiHi; wi++) {
                int l = lr + (wpix - wi * 4);
                int row = ((hi * NH_ + wi) * 4 + b) * 64 + l;
                val = val * 0.7f + 0.3f * g_att[(size_t)row * 128 + e];
            }
        }
        enh[px][e] = val;
    }
    __syncthreads();

    {
        int px = tid >> 3;
        int cg = tid & 7;
        float acc[8];
#pragma unroll
        for (int j = 0; j < 8; j++) acc[j] = fbs[cg * 8 + j];
#pragma unroll 4
        for (int e = 0; e < 128; e++) {
            float a = enh[px][e];
            const float4* bp = reinterpret_cast<const float4*>(&fcs[e][cg * 8]);
            float4 b0 = bp[0];
            float4 b1 = bp[1];
            acc[0] += a * b0.x; acc[1] += a * b0.y;
            acc[2] += a * b0.z; acc[3] += a * b0.w;
            acc[4] += a * b1.x; acc[5] += a * b1.y;
            acc[6] += a * b1.z; acc[7] += a * b1.w;
        }
#pragma unroll
        for (int j = 0; j < 8; j++)
            fw[px][cg * 8 + j] = 1.f / (1.f + __expf(-acc[j]));
    }
    __syncthreads();

    for (int s = 0; s < 16; s++) {
        int idx = tid + s * 256;
        int px = idx & 31;
        int ch = idx >> 5;
        size_t off = ((size_t)(b * 128 + ch) * HH + h) * WWID + w0 + px;
        out[off] = enh[px][ch] * fw[px][ch & 63] + vf[off];
    }
}

// ---------------------------------------------------------------------------
// Launch
// ---------------------------------------------------------------------------
extern "C" void kernel_launch(void* const* d_in, const int* in_sizes, int n_in,
                              void* d_out, int out_size)
{
    const float* vf    = (const float*)d_in[0];
    const float* mw1   = (const float*)d_in[1];
    const float* mb1   = (const float*)d_in[2];
    const float* mw2   = (const float*)d_in[3];
    const float* mb2   = (const float*)d_in[4];
    const float* aw1   = (const float*)d_in[5];
    const float* ab1   = (const float*)d_in[6];
    const float* aw2   = (const float*)d_in[7];
    const float* ab2   = (const float*)d_in[8];
    const float* ipw   = (const float*)d_in[9];   // [384,128]
    const float* ipb   = (const float*)d_in[10];
    const float* opw   = (const float*)d_in[11];  // [128,128]
    const float* opb   = (const float*)d_in[12];
    const float* fcw   = (const float*)d_in[13];  // [64,128]
    const float* fcb   = (const float*)d_in[14];
    float* out = (float*)d_out;

    void *pqkv, *po2, *patt;
    cudaGetSymbolAddress(&pqkv, g_qkv);
    cudaGetSymbolAddress(&po2,  g_o2);
    cudaGetSymbolAddress(&patt, g_att);

    dim3 cblk(16, 16);
    conv1_kernel<<<dim3(4, 8, 32), cblk>>>(vf, mw1, mb1, aw1, ab1);
    conv2_kernel<<<dim3(4, 8, 64), cblk>>>(mw2, mb2, aw2, ab2);

    // QKV: tokens (gathered from NHWC) x [384,128]^T  -> g_qkv
    gemm_tf32_kernel<true><<<dim3(3, NTOK / 128), 256>>>(
        nullptr, ipw, ipb, (float*)pqkv, 384);

    attn_kernel<<<NWB * 4, 128>>>();

    // out-proj: g_o2 [NTOK,128] x [128,128]^T -> g_att
    gemm_tf32_kernel<false><<<dim3(1, NTOK / 128), 256>>>(
        (const float*)po2, opw, opb, (float*)patt, 128);

    blend_kernel<<<dim3(4, HH, BB), 256>>>(fcw, fcb, vf, out);
}